// round 15
// baseline (speedup 1.0000x reference)
#include <cuda_runtime.h>
#include <cuda_fp16.h>
#include <mma.h>
#include <math.h>
#include <stdint.h>

using namespace nvcuda;

#define Gn 512
#define Pn 128
#define Dn 256
#define En 1024
#define Hn 8
#define HDn 32
#define DFn 1024
#define Mn (Gn*Pn)

typedef unsigned long long u64t;

// ---------------- scratch ----------------
__device__ float  g_h[(size_t)Mn*Dn];
__device__ float  g_tmp[(size_t)Mn*Dn];
__device__ float  g_qkv[(size_t)Mn*3*Dn];
__device__ __half g_x16[(size_t)Mn*Dn];
__device__ __half g_a16[(size_t)Mn*Dn];
__device__ __half g_f16[(size_t)Mn*DFn];

// packed weights: [N][K] fp16
#define W16_CONV  (Dn*Dn)
#define W16_FFN   (DFn*Dn)
#define W16_LAYER (4*W16_CONV + 2*W16_FFN)
__device__ __half g_w16[2*W16_CONV + 2*W16_LAYER];

__device__ int   g_rp[Pn+1];
__device__ int   g_ci[En+Pn];
__device__ float g_wv[En+Pn];

// ---------------- helpers ----------------
__device__ __forceinline__ uint32_t smem_u32(const void* p) {
    uint32_t a;
    asm("{ .reg .u64 t; cvta.to.shared.u64 t, %1; cvt.u32.u64 %0, t; }" : "=r"(a) : "l"(p));
    return a;
}
__device__ __forceinline__ void cp_async16(uint32_t dst, const void* src) {
    asm volatile("cp.async.cg.shared.global [%0], [%1], 16;" :: "r"(dst), "l"(src) : "memory");
}
__device__ __forceinline__ void cp_commit() {
    asm volatile("cp.async.commit_group;" ::: "memory");
}
template<int N>
__device__ __forceinline__ void cp_wait() {
    asm volatile("cp.async.wait_group %0;" :: "n"(N) : "memory");
}
__device__ __forceinline__ u64t f2pack(float lo, float hi) {
    u64t r; asm("mov.b64 %0, {%1, %2};" : "=l"(r) : "f"(lo), "f"(hi)); return r;
}
__device__ __forceinline__ float2 f2unpack(u64t v) {
    float x, y; asm("mov.b64 {%0, %1}, %2;" : "=f"(x), "=f"(y) : "l"(v));
    return make_float2(x, y);
}
__device__ __forceinline__ u64t fma2(u64t a, u64t b, u64t c) {
    u64t d; asm("fma.rn.f32x2 %0, %1, %2, %3;" : "=l"(d) : "l"(a), "l"(b), "l"(c)); return d;
}

// ---------------- fused graph setup (1 block) ----------------
__global__ void k_setup(const int* __restrict__ ei, int* rp, int* ci, float* wv) {
    __shared__ int   deg[Pn];
    __shared__ float dinv[Pn];
    __shared__ int   srp[Pn+1];
    __shared__ int   cur[Pn];
    int t = threadIdx.x;
    deg[t] = 1;
    __syncthreads();
    for (int e = t; e < En; e += Pn) atomicAdd(&deg[ei[En + e]], 1);
    __syncthreads();
    dinv[t] = rsqrtf((float)deg[t]);
    __syncthreads();
    if (t == 0) {
        int s = 0;
        for (int i = 0; i < Pn; i++) { srp[i] = s; cur[i] = s; s += deg[i]; }
        srp[Pn] = s;
    }
    __syncthreads();
    for (int e = t; e < En; e += Pn) {
        int s = ei[e], d = ei[En + e];
        int pos = atomicAdd(&cur[d], 1);
        ci[pos] = s; wv[pos] = dinv[s]*dinv[d];
    }
    {
        int pos = atomicAdd(&cur[t], 1);
        ci[pos] = t; wv[pos] = dinv[t]*dinv[t];
    }
    rp[t] = srp[t];
    if (t == 0) rp[Pn] = srp[Pn];
}

// ---------------- fused weight pack: W[K,N] fp32 -> [N][K] fp16 -------------
struct WD { const float* src; long long dst; int K; int N; };
struct WPack { WD d[14]; long long start[15]; };

__global__ void k_wprepAll(WPack p) {
    long long idx = (long long)blockIdx.x*256 + threadIdx.x;
    if (idx >= p.start[14]) return;
    int r = 0;
    #pragma unroll
    for (int i = 1; i < 14; i++) if (idx >= p.start[i]) r = i;
    long long local = idx - p.start[r];
    const WD d = p.d[r];
    int k = (int)(local / d.N), n = (int)(local - (long long)k*d.N);
    g_w16[d.dst + (size_t)n*d.K + k] = __float2half_rn(d.src[local]);
}

// ---------------- input convert ----------------
__global__ void k_acvt(const float* __restrict__ X, __half* __restrict__ S) {
    int idx = blockIdx.x*blockDim.x + threadIdx.x;
    float4 v = reinterpret_cast<const float4*>(X)[idx];
    *reinterpret_cast<__half2*>(S + (size_t)idx*4)     = __floats2half2_rn(v.x, v.y);
    *reinterpret_cast<__half2*>(S + (size_t)idx*4 + 2) = __floats2half2_rn(v.z, v.w);
}

// ---------------- fp16 WMMA GEMM, BM=BN=128, BK=64, 512 thr, 32x32 warp tile
#define TSTR 72
#define TILE16 18432
#define STAGE16 (2*TILE16)
#define GEMM16_SMEM (2*STAGE16)    // 73728 >= epilogue 128*136*4 = 69632

template<int BMODE, bool RELU, bool WF32, bool WHALF>
__global__ void __launch_bounds__(512, 2)
gemm16(const __half* __restrict__ A, long long lda,
       const __half* __restrict__ B, long long ldb,
       const float* __restrict__ b0, const float* __restrict__ b1p,
       const float* __restrict__ b2p,
       float* __restrict__ C, __half* __restrict__ Ch,
       int K, int Ntot)
{
    extern __shared__ __align__(128) char dsm[];
    const int tid = threadIdx.x;
    const int wid = tid >> 5;
    const int wm = wid & 3;       // 0..3  (32-row slice)
    const int wn = wid >> 2;      // 0..3  (32-col slice)
    const int m0 = blockIdx.y * 128;
    const int n0 = blockIdx.x * 128;
    uint32_t sbase = smem_u32(dsm);

    const int nc = K >> 6;

    wmma::fragment<wmma::accumulator, 16,16,16, float> acc[2][2];
    #pragma unroll
    for (int i = 0; i < 2; i++)
        #pragma unroll
        for (int j = 0; j < 2; j++) wmma::fill_fragment(acc[i][j], 0.f);

    auto load_chunk = [&](int c, int stage) {
        int k0 = c << 6;
        uint32_t baseA = sbase + stage*STAGE16;
        uint32_t baseB = baseA + TILE16;
        #pragma unroll
        for (int r = 0; r < 2; r++) {
            int id = tid + r*512;          // 0..1023
            int row = id >> 3, seg = id & 7;
            uint32_t soff = row*144 + seg*16;
            cp_async16(baseA + soff, A + (size_t)(m0+row)*lda + k0 + seg*8);
            cp_async16(baseB + soff, B + (size_t)(n0+row)*ldb + k0 + seg*8);
        }
        cp_commit();
    };

    load_chunk(0, 0);

    for (int c = 0; c < nc; c++) {
        const int stage = c & 1;
        cp_wait<0>();
        __syncthreads();
        if (c + 1 < nc) load_chunk(c+1, stage^1);

        const __half* At = reinterpret_cast<const __half*>(dsm + stage*STAGE16);
        const __half* Bt = At + TILE16/2;

        #pragma unroll
        for (int ks = 0; ks < 4; ks++) {
            wmma::fragment<wmma::matrix_b, 16,16,16, __half, wmma::col_major> bfr[2];
            #pragma unroll
            for (int nt = 0; nt < 2; nt++)
                wmma::load_matrix_sync(bfr[nt], Bt + (wn*32 + nt*16)*TSTR + ks*16, TSTR);
            wmma::fragment<wmma::matrix_a, 16,16,16, __half, wmma::row_major> af[2];
            #pragma unroll
            for (int mt = 0; mt < 2; mt++)
                wmma::load_matrix_sync(af[mt], At + (wm*32 + mt*16)*TSTR + ks*16, TSTR);
            #pragma unroll
            for (int mt = 0; mt < 2; mt++)
                #pragma unroll
                for (int nt = 0; nt < 2; nt++)
                    wmma::mma_sync(acc[mt][nt], af[mt], bfr[nt], acc[mt][nt]);
        }
    }
    __syncthreads();

    const float* bp = nullptr;
    int bbase = 0;
    if (BMODE == 1) { bp = b0; bbase = n0; }
    if (BMODE == 2) {
        int sel = blockIdx.x >> 1;
        bp = (sel == 0) ? b0 : ((sel == 1) ? b1p : b2p);
        bbase = (blockIdx.x & 1) * 128;
    }

    float* stg = reinterpret_cast<float*>(dsm);
    #pragma unroll
    for (int mt = 0; mt < 2; mt++)
        #pragma unroll
        for (int nt = 0; nt < 2; nt++)
            wmma::store_matrix_sync(stg + (wm*32 + mt*16)*136 + wn*32 + nt*16,
                                    acc[mt][nt], 136, wmma::mem_row_major);
    __syncthreads();

    int row = tid >> 2;
    int cb  = (tid & 3) * 32;
    const float* sr = stg + row*136 + cb;
    size_t crow = (size_t)(m0+row)*Ntot + n0 + cb;
    #pragma unroll
    for (int j = 0; j < 32; j += 4) {
        float4 v = *reinterpret_cast<const float4*>(sr + j);
        if (BMODE) {
            float4 b = *reinterpret_cast<const float4*>(bp + bbase + cb + j);
            v.x += b.x; v.y += b.y; v.z += b.z; v.w += b.w;
        }
        if (RELU) {
            v.x = fmaxf(v.x, 0.f); v.y = fmaxf(v.y, 0.f);
            v.z = fmaxf(v.z, 0.f); v.w = fmaxf(v.w, 0.f);
        }
        if (WF32) *reinterpret_cast<float4*>(C + crow + j) = v;
        if (WHALF) {
            __half* hp = Ch + crow;
            *reinterpret_cast<__half2*>(hp + j)     = __floats2half2_rn(v.x, v.y);
            *reinterpret_cast<__half2*>(hp + j + 2) = __floats2half2_rn(v.z, v.w);
        }
    }
}

// ---------------- sparse GCN aggregation (+bias +relu) ----------------------
template<bool WF32>
__global__ void __launch_bounds__(256)
agg_csr(const float* __restrict__ xw, const int* __restrict__ rp,
        const int* __restrict__ ci, const float* __restrict__ wv,
        const float* __restrict__ bias, float* __restrict__ outf,
        __half* __restrict__ sp)
{
    int warp = blockIdx.x*8 + (threadIdx.x >> 5);
    int lane = threadIdx.x & 31;
    int p = warp & 127;
    size_t gbase = (size_t)(warp & ~127) * Dn;

    float4 a0 = make_float4(0.f,0.f,0.f,0.f);
    float4 a1 = make_float4(0.f,0.f,0.f,0.f);
    int s0 = rp[p], s1 = rp[p+1];
    for (int e = s0; e < s1; e++) {
        int src = ci[e]; float w = wv[e];
        const float4* rowp = reinterpret_cast<const float4*>(xw + gbase + (size_t)src*Dn);
        float4 x0 = rowp[lane];
        float4 x1 = rowp[lane+32];
        a0.x = fmaf(w, x0.x, a0.x); a0.y = fmaf(w, x0.y, a0.y);
        a0.z = fmaf(w, x0.z, a0.z); a0.w = fmaf(w, x0.w, a0.w);
        a1.x = fmaf(w, x1.x, a1.x); a1.y = fmaf(w, x1.y, a1.y);
        a1.z = fmaf(w, x1.z, a1.z); a1.w = fmaf(w, x1.w, a1.w);
    }
    int c0 = lane*4;
    float4 b0 = *reinterpret_cast<const float4*>(bias + c0);
    float4 b1 = *reinterpret_cast<const float4*>(bias + c0 + 128);
    a0.x = fmaxf(a0.x + b0.x, 0.f); a0.y = fmaxf(a0.y + b0.y, 0.f);
    a0.z = fmaxf(a0.z + b0.z, 0.f); a0.w = fmaxf(a0.w + b0.w, 0.f);
    a1.x = fmaxf(a1.x + b1.x, 0.f); a1.y = fmaxf(a1.y + b1.y, 0.f);
    a1.z = fmaxf(a1.z + b1.z, 0.f); a1.w = fmaxf(a1.w + b1.w, 0.f);

    if (WF32) {
        float* dst = outf + (size_t)warp*Dn;
        *reinterpret_cast<float4*>(dst + c0)       = a0;
        *reinterpret_cast<float4*>(dst + c0 + 128) = a1;
    }
    __half* sprow = sp + (size_t)warp*Dn;
    *reinterpret_cast<__half2*>(sprow + c0)     = __floats2half2_rn(a0.x, a0.y);
    *reinterpret_cast<__half2*>(sprow + c0 + 2) = __floats2half2_rn(a0.z, a0.w);
    *reinterpret_cast<__half2*>(sprow + c0 + 128) = __floats2half2_rn(a1.x, a1.y);
    *reinterpret_cast<__half2*>(sprow + c0 + 130) = __floats2half2_rn(a1.z, a1.w);
}

// ---------------- attention: f32x2-packed, fp16 output ----------------------
__global__ void __launch_bounds__(128)
attn_kernel(const float* __restrict__ qkv, __half* __restrict__ sp)
{
    int head = blockIdx.x;
    int g    = blockIdx.y;
    int tid  = threadIdx.x;

    __shared__ u64t Ks[Pn][HDn/2];
    __shared__ u64t Vs[Pn][HDn/2];

    size_t base = ((size_t)g*Pn + tid)*768 + head*HDn;
    u64t qr[HDn/2];
    #pragma unroll
    for (int j = 0; j < HDn/4; j++) {
        float4 qv = reinterpret_cast<const float4*>(qkv + base)[j];
        float4 kv = reinterpret_cast<const float4*>(qkv + base + 256)[j];
        float4 vv = reinterpret_cast<const float4*>(qkv + base + 512)[j];
        qr[2*j]   = f2pack(qv.x, qv.y);
        qr[2*j+1] = f2pack(qv.z, qv.w);
        Ks[tid][2*j]   = f2pack(kv.x, kv.y);
        Ks[tid][2*j+1] = f2pack(kv.z, kv.w);
        Vs[tid][2*j]   = f2pack(vv.x, vv.y);
        Vs[tid][2*j+1] = f2pack(vv.z, vv.w);
    }
    __syncthreads();

    const float scale = 0.17677669529663687f;
    float l = 0.f;
    u64t acc[HDn/2];
    #pragma unroll
    for (int d = 0; d < HDn/2; d++) acc[d] = 0ull;

    for (int j = 0; j < Pn; j++) {
        u64t s2 = 0ull;
        #pragma unroll
        for (int d = 0; d < HDn/2; d++) s2 = fma2(qr[d], Ks[j][d], s2);
        float2 sv = f2unpack(s2);
        float e = __expf((sv.x + sv.y)*scale);
        l += e;
        u64t ee = f2pack(e, e);
        #pragma unroll
        for (int d = 0; d < HDn/2; d++) acc[d] = fma2(ee, Vs[j][d], acc[d]);
    }
    float inv = 1.f / l;
    __half* sprow = sp + ((size_t)g*Pn + tid)*Dn + head*HDn;
    #pragma unroll
    for (int d = 0; d < HDn/2; d += 2) {
        float2 p0 = f2unpack(acc[d]);
        float2 p1 = f2unpack(acc[d+1]);
        *reinterpret_cast<__half2*>(sprow + 2*d)     = __floats2half2_rn(p0.x*inv, p0.y*inv);
        *reinterpret_cast<__half2*>(sprow + 2*d + 2) = __floats2half2_rn(p1.x*inv, p1.y*inv);
    }
}

// ---------------- LayerNorm(x + t)*g + b -------------------------------------
template<bool WHALF>
__global__ void __launch_bounds__(Dn)
ln_kernel(const float* __restrict__ x, const float* __restrict__ t,
          const float* __restrict__ gam, const float* __restrict__ bet,
          float* __restrict__ out, __half* __restrict__ sp)
{
    int row = blockIdx.x;
    int f   = threadIdx.x;
    size_t idx = (size_t)row*Dn + f;
    float v = x[idx] + t[idx];

    __shared__ float sh[8];
    int lane = f & 31, w = f >> 5;

    float s = v;
    #pragma unroll
    for (int off = 16; off > 0; off >>= 1) s += __shfl_xor_sync(0xffffffffu, s, off);
    if (lane == 0) sh[w] = s;
    __syncthreads();
    float mean = 0.f;
    #pragma unroll
    for (int i = 0; i < 8; i++) mean += sh[i];
    mean *= (1.f/Dn);

    float d  = v - mean;
    float s2 = d*d;
    #pragma unroll
    for (int off = 16; off > 0; off >>= 1) s2 += __shfl_xor_sync(0xffffffffu, s2, off);
    __syncthreads();
    if (lane == 0) sh[w] = s2;
    __syncthreads();
    float var = 0.f;
    #pragma unroll
    for (int i = 0; i < 8; i++) var += sh[i];
    var *= (1.f/Dn);

    float r = rsqrtf(var + 1e-5f);
    float o = d*r*gam[f] + bet[f];
    out[idx] = o;
    if (WHALF) sp[(size_t)row*Dn + f] = __float2half_rn(o);
}

// ---------------------------------------------------------------------------
extern "C" void kernel_launch(void* const* d_in, const int* in_sizes, int n_in,
                              void* d_out, int out_size)
{
    const float* x    = (const float*)d_in[0];
    const int*   ei   = (const int*)  d_in[1];
    const float* c1W  = (const float*)d_in[6];
    const float* c1b  = (const float*)d_in[7];
    const float* c2W  = (const float*)d_in[8];
    const float* c2b  = (const float*)d_in[9];
    const float* WqA  = (const float*)d_in[10];
    const float* bqA  = (const float*)d_in[11];
    const float* WkA  = (const float*)d_in[12];
    const float* bkA  = (const float*)d_in[13];
    const float* WvA  = (const float*)d_in[14];
    const float* bvA  = (const float*)d_in[15];
    const float* WoA  = (const float*)d_in[16];
    const float* boA  = (const float*)d_in[17];
    const float* W1A  = (const float*)d_in[18];
    const float* b1A  = (const float*)d_in[19];
    const float* W2A  = (const float*)d_in[20];
    const float* b2A  = (const float*)d_in[21];
    const float* l1gA = (const float*)d_in[22];
    const float* l1bA = (const float*)d_in[23];
    const float* l2gA = (const float*)d_in[24];
    const float* l2bA = (const float*)d_in[25];
    float* out = (float*)d_out;

    float *h, *tmp, *qkv, *wv;
    __half *x16, *a16, *f16, *w16;
    int *rp, *ci;
    cudaGetSymbolAddress((void**)&h,    g_h);
    cudaGetSymbolAddress((void**)&tmp,  g_tmp);
    cudaGetSymbolAddress((void**)&qkv,  g_qkv);
    cudaGetSymbolAddress((void**)&x16,  g_x16);
    cudaGetSymbolAddress((void**)&a16,  g_a16);
    cudaGetSymbolAddress((void**)&f16,  g_f16);
    cudaGetSymbolAddress((void**)&w16,  g_w16);
    cudaGetSymbolAddress((void**)&rp,   g_rp);
    cudaGetSymbolAddress((void**)&ci,   g_ci);
    cudaGetSymbolAddress((void**)&wv,   g_wv);

    cudaFuncSetAttribute(gemm16<0,false,true ,false>, cudaFuncAttributeMaxDynamicSharedMemorySize, GEMM16_SMEM);
    cudaFuncSetAttribute(gemm16<2,false,true ,false>, cudaFuncAttributeMaxDynamicSharedMemorySize, GEMM16_SMEM);
    cudaFuncSetAttribute(gemm16<1,false,true ,false>, cudaFuncAttributeMaxDynamicSharedMemorySize, GEMM16_SMEM);
    cudaFuncSetAttribute(gemm16<1,true ,false,true >, cudaFuncAttributeMaxDynamicSharedMemorySize, GEMM16_SMEM);

    // ---- launch 0: graph setup ----
    k_setup<<<1, Pn>>>(ei, rp, ci, wv);

    // ---- launch 1: all weight packs ----
    const long long oC1 = 0, oC2 = W16_CONV;
    const long long oL  = 2*W16_CONV;
    WPack wp;
    {
        int i = 0;
        long long s = 0;
        auto add = [&](const float* src, long long dst, int K, int N) {
            wp.d[i] = {src, dst, K, N};
            wp.start[i] = s;
            s += (long long)K*N;
            i++;
        };
        add(c1W, oC1, Dn, Dn);
        add(c2W, oC2, Dn, Dn);
        for (int l = 0; l < 2; l++) {
            long long b = oL + (long long)l*W16_LAYER;
            add(WqA + (size_t)l*65536,  b,              Dn, Dn);
            add(WkA + (size_t)l*65536,  b + W16_CONV,   Dn, Dn);
            add(WvA + (size_t)l*65536,  b + 2*W16_CONV, Dn, Dn);
            add(WoA + (size_t)l*65536,  b + 3*W16_CONV, Dn, Dn);
            add(W1A + (size_t)l*262144, b + 4*W16_CONV, Dn, DFn);
            add(W2A + (size_t)l*262144, b + 4*W16_CONV + W16_FFN, DFn, Dn);
        }
        wp.start[14] = s;
    }
    k_wprepAll<<<(int)((wp.start[14] + 255)/256), 256>>>(wp);

    // ---- launch 2: input convert ----
    k_acvt<<<(Mn*64)/256, 256>>>(x, x16);

    dim3 gD(2, Mn/128);
    dim3 gQKV(6, Mn/128);
    dim3 gF1(8, Mn/128);

    // ---- GCN ----
    gemm16<0,false,true,false><<<gD, 512, GEMM16_SMEM>>>(x16, 256, w16 + oC1, 256, nullptr, nullptr, nullptr, tmp, nullptr, Dn, Dn);
    agg_csr<false><<<Mn/8, 256>>>(tmp, rp, ci, wv, c1b, nullptr, a16);
    gemm16<0,false,true,false><<<gD, 512, GEMM16_SMEM>>>(a16, 256, w16 + oC2, 256, nullptr, nullptr, nullptr, tmp, nullptr, Dn, Dn);
    agg_csr<true ><<<Mn/8, 256>>>(tmp, rp, ci, wv, c2b, h, a16);

    for (int l = 0; l < 2; l++) {
        long long b = oL + (long long)l*W16_LAYER;
        const float* bq = bqA + (size_t)l*Dn;
        const float* bk = bkA + (size_t)l*Dn;
        const float* bv = bvA + (size_t)l*Dn;
        const float* bo = boA + (size_t)l*Dn;
        const float* b1 = b1A + (size_t)l*DFn;
        const float* b2 = b2A + (size_t)l*Dn;
        const float* l1g = l1gA + (size_t)l*Dn; const float* l1b = l1bA + (size_t)l*Dn;
        const float* l2g = l2gA + (size_t)l*Dn; const float* l2b = l2bA + (size_t)l*Dn;

        gemm16<2,false,true,false><<<gQKV, 512, GEMM16_SMEM>>>(a16, 256, w16 + b, 256, bq, bk, bv, qkv, nullptr, Dn, 768);

        attn_kernel<<<dim3(Hn, Gn), 128>>>(qkv, a16);

        gemm16<1,false,true,false><<<gD, 512, GEMM16_SMEM>>>(a16, 256, w16 + b + 3*W16_CONV, 256, bo, nullptr, nullptr, tmp, nullptr, Dn, Dn);
        ln_kernel<true><<<Mn, Dn>>>(h, tmp, l1g, l1b, h, a16);

        gemm16<1,true,false,true><<<gF1, 512, GEMM16_SMEM>>>(a16, 256, w16 + b + 4*W16_CONV, 256, b1, nullptr, nullptr, nullptr, f16, Dn, DFn);
        gemm16<1,false,true,false><<<gD, 512, GEMM16_SMEM>>>(f16, 1024, w16 + b + 4*W16_CONV + W16_FFN, 1024, b2, nullptr, nullptr, tmp, nullptr, DFn, Dn);

        if (l == 0) ln_kernel<true ><<<Mn, Dn>>>(h, tmp, l2g, l2b, h, a16);
        else        ln_kernel<false><<<Mn, Dn>>>(h, tmp, l2g, l2b, out, nullptr);
    }
}

// round 16
// speedup vs baseline: 1.0706x; 1.0706x over previous
#include <cuda_runtime.h>
#include <cuda_fp16.h>
#include <mma.h>
#include <math.h>
#include <stdint.h>

using namespace nvcuda;

#define Gn 512
#define Pn 128
#define Dn 256
#define En 1024
#define Hn 8
#define HDn 32
#define DFn 1024
#define Mn (Gn*Pn)

typedef unsigned long long u64t;

// ---------------- scratch ----------------
__device__ float  g_h[(size_t)Mn*Dn];
__device__ float  g_tmp[(size_t)Mn*Dn];
__device__ __half g_qkv16[(size_t)Mn*3*Dn];
__device__ __half g_x16[(size_t)Mn*Dn];
__device__ __half g_a16[(size_t)Mn*Dn];
__device__ __half g_f16[(size_t)Mn*DFn];

// packed weights: [N][K] fp16
#define W16_CONV  (Dn*Dn)
#define W16_FFN   (DFn*Dn)
#define W16_LAYER (4*W16_CONV + 2*W16_FFN)
__device__ __half g_w16[2*W16_CONV + 2*W16_LAYER];

__device__ int   g_rp[Pn+1];
__device__ int   g_ci[En+Pn];
__device__ float g_wv[En+Pn];

// ---------------- helpers ----------------
__device__ __forceinline__ uint32_t smem_u32(const void* p) {
    uint32_t a;
    asm("{ .reg .u64 t; cvta.to.shared.u64 t, %1; cvt.u32.u64 %0, t; }" : "=r"(a) : "l"(p));
    return a;
}
__device__ __forceinline__ void cp_async16(uint32_t dst, const void* src) {
    asm volatile("cp.async.cg.shared.global [%0], [%1], 16;" :: "r"(dst), "l"(src) : "memory");
}
__device__ __forceinline__ void cp_commit() {
    asm volatile("cp.async.commit_group;" ::: "memory");
}
template<int N>
__device__ __forceinline__ void cp_wait() {
    asm volatile("cp.async.wait_group %0;" :: "n"(N) : "memory");
}
__device__ __forceinline__ u64t f2pack(float lo, float hi) {
    u64t r; asm("mov.b64 %0, {%1, %2};" : "=l"(r) : "f"(lo), "f"(hi)); return r;
}
__device__ __forceinline__ float2 f2unpack(u64t v) {
    float x, y; asm("mov.b64 {%0, %1}, %2;" : "=f"(x), "=f"(y) : "l"(v));
    return make_float2(x, y);
}
__device__ __forceinline__ u64t fma2(u64t a, u64t b, u64t c) {
    u64t d; asm("fma.rn.f32x2 %0, %1, %2, %3;" : "=l"(d) : "l"(a), "l"(b), "l"(c)); return d;
}

// ---------------- fused graph setup (1 block) ----------------
__global__ void k_setup(const int* __restrict__ ei, int* rp, int* ci, float* wv) {
    __shared__ int   deg[Pn];
    __shared__ float dinv[Pn];
    __shared__ int   srp[Pn+1];
    __shared__ int   cur[Pn];
    int t = threadIdx.x;
    deg[t] = 1;
    __syncthreads();
    for (int e = t; e < En; e += Pn) atomicAdd(&deg[ei[En + e]], 1);
    __syncthreads();
    dinv[t] = rsqrtf((float)deg[t]);
    __syncthreads();
    if (t == 0) {
        int s = 0;
        for (int i = 0; i < Pn; i++) { srp[i] = s; cur[i] = s; s += deg[i]; }
        srp[Pn] = s;
    }
    __syncthreads();
    for (int e = t; e < En; e += Pn) {
        int s = ei[e], d = ei[En + e];
        int pos = atomicAdd(&cur[d], 1);
        ci[pos] = s; wv[pos] = dinv[s]*dinv[d];
    }
    {
        int pos = atomicAdd(&cur[t], 1);
        ci[pos] = t; wv[pos] = dinv[t]*dinv[t];
    }
    rp[t] = srp[t];
    if (t == 0) rp[Pn] = srp[Pn];
}

// ---------------- fused weight pack: W[K,N] fp32 -> [N][K] fp16 -------------
struct WD { const float* src; long long dst; int K; int N; };
struct WPack { WD d[14]; long long start[15]; };

__global__ void k_wprepAll(WPack p) {
    long long idx = (long long)blockIdx.x*256 + threadIdx.x;
    if (idx >= p.start[14]) return;
    int r = 0;
    #pragma unroll
    for (int i = 1; i < 14; i++) if (idx >= p.start[i]) r = i;
    long long local = idx - p.start[r];
    const WD d = p.d[r];
    int k = (int)(local / d.N), n = (int)(local - (long long)k*d.N);
    g_w16[d.dst + (size_t)n*d.K + k] = __float2half_rn(d.src[local]);
}

// ---------------- input convert ----------------
__global__ void k_acvt(const float* __restrict__ X, __half* __restrict__ S) {
    int idx = blockIdx.x*blockDim.x + threadIdx.x;
    float4 v = reinterpret_cast<const float4*>(X)[idx];
    *reinterpret_cast<__half2*>(S + (size_t)idx*4)     = __floats2half2_rn(v.x, v.y);
    *reinterpret_cast<__half2*>(S + (size_t)idx*4 + 2) = __floats2half2_rn(v.z, v.w);
}

// ---------------- fp16 WMMA GEMM, BM=BN=128, BK=64, 256 thr, 64x32 tile -----
// DIRECT: bias pre-loaded into accumulators; direct wmma store to C (fp32).
// else: staged epilogue with bias/relu and fp16 output.
#define TSTR 72
#define TILE16 18432
#define STAGE16 (2*TILE16)
#define GEMM16_SMEM (2*STAGE16)    // 73728 >= epilogue 128*136*4 = 69632

template<int BMODE, bool RELU, bool WF32, bool WHALF, bool DIRECT>
__global__ void __launch_bounds__(256, 2)
gemm16(const __half* __restrict__ A, long long lda,
       const __half* __restrict__ B, long long ldb,
       const float* __restrict__ b0, const float* __restrict__ b1p,
       const float* __restrict__ b2p,
       float* __restrict__ C, __half* __restrict__ Ch,
       int K, int Ntot)
{
    extern __shared__ __align__(128) char dsm[];
    const int tid = threadIdx.x;
    const int wid = tid >> 5;
    const int wm = wid & 1;       // 0..1  (64-row slice)
    const int wn = wid >> 1;      // 0..3  (32-col slice)
    const int m0 = blockIdx.y * 128;
    const int n0 = blockIdx.x * 128;
    uint32_t sbase = smem_u32(dsm);

    const int nc = K >> 6;

    wmma::fragment<wmma::accumulator, 16,16,16, float> acc[4][2];

    if (DIRECT && BMODE == 1) {
        // bias tile: 16 rows x 128 cols (identical rows), stride 136
        float* bt = reinterpret_cast<float*>(dsm);
        #pragma unroll
        for (int r = 0; r < 16; r++)
            for (int c = tid; c < 128; c += 256)
                bt[r*136 + c] = b0[n0 + c];
        __syncthreads();
        wmma::fragment<wmma::accumulator, 16,16,16, float> binit[2];
        #pragma unroll
        for (int nt = 0; nt < 2; nt++)
            wmma::load_matrix_sync(binit[nt], bt + wn*32 + nt*16, 136, wmma::mem_row_major);
        #pragma unroll
        for (int mt = 0; mt < 4; mt++)
            #pragma unroll
            for (int nt = 0; nt < 2; nt++) acc[mt][nt] = binit[nt];
        __syncthreads();   // tile reads done before cp.async overwrites
    } else {
        #pragma unroll
        for (int i = 0; i < 4; i++)
            #pragma unroll
            for (int j = 0; j < 2; j++) wmma::fill_fragment(acc[i][j], 0.f);
    }

    auto load_chunk = [&](int c, int stage) {
        int k0 = c << 6;
        uint32_t baseA = sbase + stage*STAGE16;
        uint32_t baseB = baseA + TILE16;
        #pragma unroll
        for (int r = 0; r < 4; r++) {
            int id = tid + r*256;          // 0..1023
            int row = id >> 3, seg = id & 7;
            uint32_t soff = row*144 + seg*16;
            cp_async16(baseA + soff, A + (size_t)(m0+row)*lda + k0 + seg*8);
            cp_async16(baseB + soff, B + (size_t)(n0+row)*ldb + k0 + seg*8);
        }
        cp_commit();
    };

    load_chunk(0, 0);

    for (int c = 0; c < nc; c++) {
        const int stage = c & 1;
        cp_wait<0>();
        __syncthreads();
        if (c + 1 < nc) load_chunk(c+1, stage^1);

        const __half* At = reinterpret_cast<const __half*>(dsm + stage*STAGE16);
        const __half* Bt = At + TILE16/2;

        #pragma unroll
        for (int ks = 0; ks < 4; ks++) {
            wmma::fragment<wmma::matrix_b, 16,16,16, __half, wmma::col_major> bfr[2];
            #pragma unroll
            for (int nt = 0; nt < 2; nt++)
                wmma::load_matrix_sync(bfr[nt], Bt + (wn*32 + nt*16)*TSTR + ks*16, TSTR);
            wmma::fragment<wmma::matrix_a, 16,16,16, __half, wmma::row_major> af[4];
            #pragma unroll
            for (int mt = 0; mt < 4; mt++)
                wmma::load_matrix_sync(af[mt], At + (wm*64 + mt*16)*TSTR + ks*16, TSTR);
            #pragma unroll
            for (int mt = 0; mt < 4; mt++)
                #pragma unroll
                for (int nt = 0; nt < 2; nt++)
                    wmma::mma_sync(acc[mt][nt], af[mt], bfr[nt], acc[mt][nt]);
        }
    }

    if (DIRECT) {
        // direct store to global: bias already in acc, no relu needed
        #pragma unroll
        for (int mt = 0; mt < 4; mt++)
            #pragma unroll
            for (int nt = 0; nt < 2; nt++)
                wmma::store_matrix_sync(
                    C + (size_t)(m0 + wm*64 + mt*16)*Ntot + n0 + wn*32 + nt*16,
                    acc[mt][nt], Ntot, wmma::mem_row_major);
        return;
    }

    __syncthreads();

    const float* bp = nullptr;
    int bbase = 0;
    if (BMODE == 1) { bp = b0; bbase = n0; }
    if (BMODE == 2) {
        int sel = blockIdx.x >> 1;
        bp = (sel == 0) ? b0 : ((sel == 1) ? b1p : b2p);
        bbase = (blockIdx.x & 1) * 128;
    }

    float* stg = reinterpret_cast<float*>(dsm);
    #pragma unroll
    for (int mt = 0; mt < 4; mt++)
        #pragma unroll
        for (int nt = 0; nt < 2; nt++)
            wmma::store_matrix_sync(stg + (wm*64 + mt*16)*136 + wn*32 + nt*16,
                                    acc[mt][nt], 136, wmma::mem_row_major);
    __syncthreads();

    int row = tid >> 1;
    int cb  = (tid & 1) * 64;
    const float* sr = stg + row*136 + cb;
    size_t crow = (size_t)(m0+row)*Ntot + n0 + cb;
    #pragma unroll
    for (int j = 0; j < 64; j += 4) {
        float4 v = *reinterpret_cast<const float4*>(sr + j);
        if (BMODE) {
            float4 b = *reinterpret_cast<const float4*>(bp + bbase + cb + j);
            v.x += b.x; v.y += b.y; v.z += b.z; v.w += b.w;
        }
        if (RELU) {
            v.x = fmaxf(v.x, 0.f); v.y = fmaxf(v.y, 0.f);
            v.z = fmaxf(v.z, 0.f); v.w = fmaxf(v.w, 0.f);
        }
        if (WF32) *reinterpret_cast<float4*>(C + crow + j) = v;
        if (WHALF) {
            __half* hp = Ch + crow;
            *reinterpret_cast<__half2*>(hp + j)     = __floats2half2_rn(v.x, v.y);
            *reinterpret_cast<__half2*>(hp + j + 2) = __floats2half2_rn(v.z, v.w);
        }
    }
}

// ---------------- sparse GCN aggregation (+bias +relu) ----------------------
template<bool WF32>
__global__ void __launch_bounds__(256)
agg_csr(const float* __restrict__ xw, const int* __restrict__ rp,
        const int* __restrict__ ci, const float* __restrict__ wv,
        const float* __restrict__ bias, float* __restrict__ outf,
        __half* __restrict__ sp)
{
    int warp = blockIdx.x*8 + (threadIdx.x >> 5);
    int lane = threadIdx.x & 31;
    int p = warp & 127;
    size_t gbase = (size_t)(warp & ~127) * Dn;

    float4 a0 = make_float4(0.f,0.f,0.f,0.f);
    float4 a1 = make_float4(0.f,0.f,0.f,0.f);
    int s0 = rp[p], s1 = rp[p+1];
    for (int e = s0; e < s1; e++) {
        int src = ci[e]; float w = wv[e];
        const float4* rowp = reinterpret_cast<const float4*>(xw + gbase + (size_t)src*Dn);
        float4 x0 = rowp[lane];
        float4 x1 = rowp[lane+32];
        a0.x = fmaf(w, x0.x, a0.x); a0.y = fmaf(w, x0.y, a0.y);
        a0.z = fmaf(w, x0.z, a0.z); a0.w = fmaf(w, x0.w, a0.w);
        a1.x = fmaf(w, x1.x, a1.x); a1.y = fmaf(w, x1.y, a1.y);
        a1.z = fmaf(w, x1.z, a1.z); a1.w = fmaf(w, x1.w, a1.w);
    }
    int c0 = lane*4;
    float4 b0 = *reinterpret_cast<const float4*>(bias + c0);
    float4 b1 = *reinterpret_cast<const float4*>(bias + c0 + 128);
    a0.x = fmaxf(a0.x + b0.x, 0.f); a0.y = fmaxf(a0.y + b0.y, 0.f);
    a0.z = fmaxf(a0.z + b0.z, 0.f); a0.w = fmaxf(a0.w + b0.w, 0.f);
    a1.x = fmaxf(a1.x + b1.x, 0.f); a1.y = fmaxf(a1.y + b1.y, 0.f);
    a1.z = fmaxf(a1.z + b1.z, 0.f); a1.w = fmaxf(a1.w + b1.w, 0.f);

    if (WF32) {
        float* dst = outf + (size_t)warp*Dn;
        *reinterpret_cast<float4*>(dst + c0)       = a0;
        *reinterpret_cast<float4*>(dst + c0 + 128) = a1;
    }
    __half* sprow = sp + (size_t)warp*Dn;
    *reinterpret_cast<__half2*>(sprow + c0)     = __floats2half2_rn(a0.x, a0.y);
    *reinterpret_cast<__half2*>(sprow + c0 + 2) = __floats2half2_rn(a0.z, a0.w);
    *reinterpret_cast<__half2*>(sprow + c0 + 128) = __floats2half2_rn(a1.x, a1.y);
    *reinterpret_cast<__half2*>(sprow + c0 + 130) = __floats2half2_rn(a1.z, a1.w);
}

// ---------------- attention: fp16 qkv in, f32x2 compute, fp16 out -----------
__global__ void __launch_bounds__(128)
attn_kernel(const __half* __restrict__ qkv, __half* __restrict__ sp)
{
    int head = blockIdx.x;
    int g    = blockIdx.y;
    int tid  = threadIdx.x;

    __shared__ u64t Ks[Pn][HDn/2];
    __shared__ u64t Vs[Pn][HDn/2];

    size_t base = ((size_t)g*Pn + tid)*768 + head*HDn;
    u64t qr[HDn/2];
    #pragma unroll
    for (int j = 0; j < 4; j++) {       // 4 x 16B = 32 halves
        uint4 uq = reinterpret_cast<const uint4*>(qkv + base)[j];
        uint4 uk = reinterpret_cast<const uint4*>(qkv + base + 256)[j];
        uint4 uv = reinterpret_cast<const uint4*>(qkv + base + 512)[j];
        const __half2* hq = reinterpret_cast<const __half2*>(&uq);
        const __half2* hk = reinterpret_cast<const __half2*>(&uk);
        const __half2* hv = reinterpret_cast<const __half2*>(&uv);
        #pragma unroll
        for (int t = 0; t < 4; t++) {
            float2 fq = __half22float2(hq[t]);
            float2 fk = __half22float2(hk[t]);
            float2 fv = __half22float2(hv[t]);
            qr[j*4+t] = f2pack(fq.x, fq.y);
            Ks[tid][j*4+t] = f2pack(fk.x, fk.y);
            Vs[tid][j*4+t] = f2pack(fv.x, fv.y);
        }
    }
    __syncthreads();

    const float scale = 0.17677669529663687f;
    float l = 0.f;
    u64t acc[HDn/2];
    #pragma unroll
    for (int d = 0; d < HDn/2; d++) acc[d] = 0ull;

    for (int j = 0; j < Pn; j++) {
        u64t s2 = 0ull;
        #pragma unroll
        for (int d = 0; d < HDn/2; d++) s2 = fma2(qr[d], Ks[j][d], s2);
        float2 sv = f2unpack(s2);
        float e = __expf((sv.x + sv.y)*scale);
        l += e;
        u64t ee = f2pack(e, e);
        #pragma unroll
        for (int d = 0; d < HDn/2; d++) acc[d] = fma2(ee, Vs[j][d], acc[d]);
    }
    float inv = 1.f / l;
    __half* sprow = sp + ((size_t)g*Pn + tid)*Dn + head*HDn;
    #pragma unroll
    for (int d = 0; d < HDn/2; d += 2) {
        float2 p0 = f2unpack(acc[d]);
        float2 p1 = f2unpack(acc[d+1]);
        *reinterpret_cast<__half2*>(sprow + 2*d)     = __floats2half2_rn(p0.x*inv, p0.y*inv);
        *reinterpret_cast<__half2*>(sprow + 2*d + 2) = __floats2half2_rn(p1.x*inv, p1.y*inv);
    }
}

// ---------------- LayerNorm(x + t)*g + b -------------------------------------
template<bool WHALF>
__global__ void __launch_bounds__(Dn)
ln_kernel(const float* __restrict__ x, const float* __restrict__ t,
          const float* __restrict__ gam, const float* __restrict__ bet,
          float* __restrict__ out, __half* __restrict__ sp)
{
    int row = blockIdx.x;
    int f   = threadIdx.x;
    size_t idx = (size_t)row*Dn + f;
    float v = x[idx] + t[idx];

    __shared__ float sh[8];
    int lane = f & 31, w = f >> 5;

    float s = v;
    #pragma unroll
    for (int off = 16; off > 0; off >>= 1) s += __shfl_xor_sync(0xffffffffu, s, off);
    if (lane == 0) sh[w] = s;
    __syncthreads();
    float mean = 0.f;
    #pragma unroll
    for (int i = 0; i < 8; i++) mean += sh[i];
    mean *= (1.f/Dn);

    float d  = v - mean;
    float s2 = d*d;
    #pragma unroll
    for (int off = 16; off > 0; off >>= 1) s2 += __shfl_xor_sync(0xffffffffu, s2, off);
    __syncthreads();
    if (lane == 0) sh[w] = s2;
    __syncthreads();
    float var = 0.f;
    #pragma unroll
    for (int i = 0; i < 8; i++) var += sh[i];
    var *= (1.f/Dn);

    float r = rsqrtf(var + 1e-5f);
    float o = d*r*gam[f] + bet[f];
    out[idx] = o;
    if (WHALF) sp[(size_t)row*Dn + f] = __float2half_rn(o);
}

// ---------------------------------------------------------------------------
extern "C" void kernel_launch(void* const* d_in, const int* in_sizes, int n_in,
                              void* d_out, int out_size)
{
    const float* x    = (const float*)d_in[0];
    const int*   ei   = (const int*)  d_in[1];
    const float* c1W  = (const float*)d_in[6];
    const float* c1b  = (const float*)d_in[7];
    const float* c2W  = (const float*)d_in[8];
    const float* c2b  = (const float*)d_in[9];
    const float* WqA  = (const float*)d_in[10];
    const float* bqA  = (const float*)d_in[11];
    const float* WkA  = (const float*)d_in[12];
    const float* bkA  = (const float*)d_in[13];
    const float* WvA  = (const float*)d_in[14];
    const float* bvA  = (const float*)d_in[15];
    const float* WoA  = (const float*)d_in[16];
    const float* boA  = (const float*)d_in[17];
    const float* W1A  = (const float*)d_in[18];
    const float* b1A  = (const float*)d_in[19];
    const float* W2A  = (const float*)d_in[20];
    const float* b2A  = (const float*)d_in[21];
    const float* l1gA = (const float*)d_in[22];
    const float* l1bA = (const float*)d_in[23];
    const float* l2gA = (const float*)d_in[24];
    const float* l2bA = (const float*)d_in[25];
    float* out = (float*)d_out;

    float *h, *tmp, *wv;
    __half *qkv16, *x16, *a16, *f16, *w16;
    int *rp, *ci;
    cudaGetSymbolAddress((void**)&h,      g_h);
    cudaGetSymbolAddress((void**)&tmp,    g_tmp);
    cudaGetSymbolAddress((void**)&qkv16,  g_qkv16);
    cudaGetSymbolAddress((void**)&x16,    g_x16);
    cudaGetSymbolAddress((void**)&a16,    g_a16);
    cudaGetSymbolAddress((void**)&f16,    g_f16);
    cudaGetSymbolAddress((void**)&w16,    g_w16);
    cudaGetSymbolAddress((void**)&rp,     g_rp);
    cudaGetSymbolAddress((void**)&ci,     g_ci);
    cudaGetSymbolAddress((void**)&wv,     g_wv);

    cudaFuncSetAttribute(gemm16<0,false,true ,false,true >, cudaFuncAttributeMaxDynamicSharedMemorySize, GEMM16_SMEM);
    cudaFuncSetAttribute(gemm16<1,false,true ,false,true >, cudaFuncAttributeMaxDynamicSharedMemorySize, GEMM16_SMEM);
    cudaFuncSetAttribute(gemm16<2,false,false,true ,false>, cudaFuncAttributeMaxDynamicSharedMemorySize, GEMM16_SMEM);
    cudaFuncSetAttribute(gemm16<1,true ,false,true ,false>, cudaFuncAttributeMaxDynamicSharedMemorySize, GEMM16_SMEM);

    // ---- launch 0: graph setup ----
    k_setup<<<1, Pn>>>(ei, rp, ci, wv);

    // ---- launch 1: all weight packs ----
    const long long oC1 = 0, oC2 = W16_CONV;
    const long long oL  = 2*W16_CONV;
    WPack wp;
    {
        int i = 0;
        long long s = 0;
        auto add = [&](const float* src, long long dst, int K, int N) {
            wp.d[i] = {src, dst, K, N};
            wp.start[i] = s;
            s += (long long)K*N;
            i++;
        };
        add(c1W, oC1, Dn, Dn);
        add(c2W, oC2, Dn, Dn);
        for (int l = 0; l < 2; l++) {
            long long b = oL + (long long)l*W16_LAYER;
            add(WqA + (size_t)l*65536,  b,              Dn, Dn);
            add(WkA + (size_t)l*65536,  b + W16_CONV,   Dn, Dn);
            add(WvA + (size_t)l*65536,  b + 2*W16_CONV, Dn, Dn);
            add(WoA + (size_t)l*65536,  b + 3*W16_CONV, Dn, Dn);
            add(W1A + (size_t)l*262144, b + 4*W16_CONV, Dn, DFn);
            add(W2A + (size_t)l*262144, b + 4*W16_CONV + W16_FFN, DFn, Dn);
        }
        wp.start[14] = s;
    }
    k_wprepAll<<<(int)((wp.start[14] + 255)/256), 256>>>(wp);

    // ---- launch 2: input convert ----
    k_acvt<<<(Mn*64)/256, 256>>>(x, x16);

    dim3 gD(2, Mn/128);
    dim3 gQKV(6, Mn/128);
    dim3 gF1(8, Mn/128);

    // ---- GCN (direct-store GEMMs, no bias) ----
    gemm16<0,false,true,false,true><<<gD, 256, GEMM16_SMEM>>>(x16, 256, w16 + oC1, 256, nullptr, nullptr, nullptr, tmp, nullptr, Dn, Dn);
    agg_csr<false><<<Mn/8, 256>>>(tmp, rp, ci, wv, c1b, nullptr, a16);
    gemm16<0,false,true,false,true><<<gD, 256, GEMM16_SMEM>>>(a16, 256, w16 + oC2, 256, nullptr, nullptr, nullptr, tmp, nullptr, Dn, Dn);
    agg_csr<true ><<<Mn/8, 256>>>(tmp, rp, ci, wv, c2b, h, a16);

    for (int l = 0; l < 2; l++) {
        long long b = oL + (long long)l*W16_LAYER;
        const float* bq = bqA + (size_t)l*Dn;
        const float* bk = bkA + (size_t)l*Dn;
        const float* bv = bvA + (size_t)l*Dn;
        const float* bo = boA + (size_t)l*Dn;
        const float* b1 = b1A + (size_t)l*DFn;
        const float* b2 = b2A + (size_t)l*Dn;
        const float* l1g = l1gA + (size_t)l*Dn; const float* l1b = l1bA + (size_t)l*Dn;
        const float* l2g = l2gA + (size_t)l*Dn; const float* l2b = l2bA + (size_t)l*Dn;

        // QKV: staged epilogue, fp16 output (L2-resident)
        gemm16<2,false,false,true,false><<<gQKV, 256, GEMM16_SMEM>>>(a16, 256, w16 + b, 256, bq, bk, bv, nullptr, qkv16, Dn, 768);

        attn_kernel<<<dim3(Hn, Gn), 128>>>(qkv16, a16);

        // attn-out: direct-store with bias-in-acc
        gemm16<1,false,true,false,true><<<gD, 256, GEMM16_SMEM>>>(a16, 256, w16 + b + 3*W16_CONV, 256, bo, nullptr, nullptr, tmp, nullptr, Dn, Dn);
        ln_kernel<true><<<Mn, Dn>>>(h, tmp, l1g, l1b, h, a16);

        // FFN1: staged (relu + fp16 out)
        gemm16<1,true,false,true,false><<<gF1, 256, GEMM16_SMEM>>>(a16, 256, w16 + b + 4*W16_CONV, 256, b1, nullptr, nullptr, nullptr, f16, Dn, DFn);
        // FFN2: direct-store with bias-in-acc
        gemm16<1,false,true,false,true><<<gD, 256, GEMM16_SMEM>>>(f16, 1024, w16 + b + 4*W16_CONV + W16_FFN, 1024, b2, nullptr, nullptr, tmp, nullptr, DFn, Dn);

        if (l == 0) ln_kernel<true ><<<Mn, Dn>>>(h, tmp, l2g, l2b, h, a16);
        else        ln_kernel<false><<<Mn, Dn>>>(h, tmp, l2g, l2b, out, nullptr);
    }
}